// round 5
// baseline (speedup 1.0000x reference)
#include <cuda_runtime.h>

// Spatial correlation sampler: out[b][dy][dx][y][x] =
//   sum_c in1[b,c,y,x] * in2[b,c,y+dy-4,x+dx-4]   (zero padded), dy,dx in 0..8
//
// Round-5: anti-diagonal decomposition (thread = one in2 row r, one dy-group
// of 3, 4 x-pixels, 9 dx -> 27 f32x2 accumulators) + EXPLICIT cross-iteration
// software pipeline: two disjoint register buffer sets so channel c+1's loads
// issue while channel c's FMAs execute (kills the WAR serialization that kept
// issue at 25% in rounds 3-4).

#define CC 128
#define HH 96
#define WW 128
#define HW (HH * WW)

typedef unsigned long long ull;

__device__ __forceinline__ void fma2(ull& acc, ull a, ull b) {
    asm("fma.rn.f32x2 %0, %1, %2, %0;" : "+l"(acc) : "l"(a), "l"(b));
}

// pair (lo = hi of a, hi = lo of b)
__device__ __forceinline__ ull pkmid(ull a, ull b) {
    ull r;
    asm("{ .reg .b32 al, ah, bl, bh;\n\t"
        "  mov.b64 {al, ah}, %1;\n\t"
        "  mov.b64 {bl, bh}, %2;\n\t"
        "  mov.b64 %0, {ah, bl}; }"
        : "=l"(r) : "l"(a), "l"(b));
    return r;
}

__device__ __forceinline__ float2 unpk(ull v) {
    unsigned lo, hi;
    asm("mov.b64 {%0,%1}, %2;" : "=r"(lo), "=r"(hi) : "l"(v));
    return make_float2(__uint_as_float(lo), __uint_as_float(hi));
}

struct Buf {
    ulonglong2 L, M, R, A0, A1, A2;
};

__global__ __launch_bounds__(288, 1) void corr_kernel(
    const float* __restrict__ in1,
    const float* __restrict__ in2,
    float* __restrict__ out)
{
    const int lane = threadIdx.x & 31;
    const int w    = threadIdx.x >> 5;        // 0..8
    const int g    = w % 3;                   // dy group: dy = 3g..3g+2
    const int ri   = w / 3;                   // 0..2 within the r-tile
    const int b    = blockIdx.y;
    const int r    = blockIdx.x * 3 + ri - 4; // in2 row, -4..100
    const int x0   = lane * 4;

    const int   rc    = r < 0 ? 0 : (r > HH - 1 ? HH - 1 : r);
    const float rowok = (r >= 0 && r < HH) ? 1.0f : 0.0f;

    int  yv[3], yc[3];
    bool yok[3];
    #pragma unroll
    for (int t = 0; t < 3; t++) {
        const int y = r + 4 - (3 * g + t);
        yv[t]  = y;
        yok[t] = (y >= 0 && y < HH);
        yc[t]  = y < 0 ? 0 : (y > HH - 1 ? HH - 1 : y);
    }

    const int offL = (lane == 0)  ? 0 : -4;
    const int offR = (lane == 31) ? 0 :  4;

    ull acc[3][9][2];
    #pragma unroll
    for (int t = 0; t < 3; t++)
        #pragma unroll
        for (int d = 0; d < 9; d++) {
            acc[t][d][0] = 0ull;
            acc[t][d][1] = 0ull;
        }

    const float* p2  = in2 + ((size_t)b * CC) * HW + (size_t)rc   * WW + x0;
    const float* p1a = in1 + ((size_t)b * CC) * HW + (size_t)yc[0] * WW + x0;
    const float* p1b = in1 + ((size_t)b * CC) * HW + (size_t)yc[1] * WW + x0;
    const float* p1c = in1 + ((size_t)b * CC) * HW + (size_t)yc[2] * WW + x0;

    // loads for one channel into a buffer set (6 independent LDG.128)
    #define LOADG(B, cc)                                                   \
        do {                                                               \
            const size_t o = (size_t)(cc) * HW;                            \
            (B).L  = *(const ulonglong2*)(p2  + o + offL);                 \
            (B).M  = *(const ulonglong2*)(p2  + o);                        \
            (B).R  = *(const ulonglong2*)(p2  + o + offR);                 \
            (B).A0 = *(const ulonglong2*)(p1a + o);                        \
            (B).A1 = *(const ulonglong2*)(p1b + o);                        \
            (B).A2 = *(const ulonglong2*)(p1c + o);                        \
        } while (0)

    // pack + 54 FFMA2 from one buffer set
    #define COMPUTE(B)                                                     \
        do {                                                               \
            ull wp[11];                                                    \
            wp[0] = (B).L.x;  wp[2] = (B).L.y;  wp[4]  = (B).M.x;          \
            wp[6] = (B).M.y;  wp[8] = (B).R.x;  wp[10] = (B).R.y;          \
            wp[1] = pkmid((B).L.x, (B).L.y);                               \
            wp[3] = pkmid((B).L.y, (B).M.x);                               \
            wp[5] = pkmid((B).M.x, (B).M.y);                               \
            wp[7] = pkmid((B).M.y, (B).R.x);                               \
            wp[9] = pkmid((B).R.x, (B).R.y);                               \
            _Pragma("unroll")                                              \
            for (int d = 0; d < 9; d++) {                                  \
                fma2(acc[0][d][0], (B).A0.x, wp[d]);                       \
                fma2(acc[0][d][1], (B).A0.y, wp[d + 2]);                   \
                fma2(acc[1][d][0], (B).A1.x, wp[d]);                       \
                fma2(acc[1][d][1], (B).A1.y, wp[d + 2]);                   \
                fma2(acc[2][d][0], (B).A2.x, wp[d]);                       \
                fma2(acc[2][d][1], (B).A2.y, wp[d + 2]);                   \
            }                                                              \
        } while (0)

    Buf b0, b1;
    LOADG(b0, 0);

    // steady state: next channel's loads issue before this channel's FMAs
    #pragma unroll 1
    for (int c = 0; c < CC - 2; c += 2) {
        LOADG(b1, c + 1);
        COMPUTE(b0);
        LOADG(b0, c + 2);
        COMPUTE(b1);
    }
    // tail: b0 holds channel CC-2
    LOADG(b1, CC - 1);
    COMPUTE(b0);
    COMPUTE(b1);

    #undef LOADG
    #undef COMPUTE

    // -------- epilogue: mask padded contributions to exact zeros --------
    #pragma unroll
    for (int t = 0; t < 3; t++) {
        if (!yok[t]) continue;                 // warp-uniform
        const int dy = 3 * g + t;
        #pragma unroll
        for (int d = 0; d < 9; d++) {
            const float2 lo = unpk(acc[t][d][0]);
            const float2 hi = unpk(acc[t][d][1]);
            float m[4];
            #pragma unroll
            for (int px = 0; px < 4; px++) {
                const int xs = x0 + px + d - 4;
                m[px] = (xs >= 0 && xs < WW) ? rowok : 0.0f;
            }
            float* po = out + (((((size_t)b * 9 + dy) * 9 + d) * HH + yv[t]) * WW) + x0;
            *(float4*)po = make_float4(lo.x * m[0], lo.y * m[1],
                                       hi.x * m[2], hi.y * m[3]);
        }
    }
}

extern "C" void kernel_launch(void* const* d_in, const int* in_sizes, int n_in,
                              void* d_out, int out_size)
{
    const float* in1 = (const float*)d_in[0];
    const float* in2 = (const float*)d_in[1];
    float* out = (float*)d_out;

    // blockIdx.x = r-tile (35 tiles cover r = -4..100), blockIdx.y = batch
    dim3 grid(35, 8, 1);
    corr_kernel<<<grid, 288>>>(in1, in2, out);
}

// round 6
// speedup vs baseline: 1.4138x; 1.4138x over previous
#include <cuda_runtime.h>
#include <cstdint>

// Spatial correlation sampler: out[b][dy][dx][y][x] =
//   sum_c in1[b,c,y,x] * in2[b,c,y+dy-4,x+dx-4]   (zero padded), dy,dx in 0..8
//
// Round-6: anti-diagonal decomposition (warp = one in2 row r, one dy-group of
// 3, lane = 4 x-pixels, all 9 dx -> 27 f32x2 accumulators) with a cp.async
// (LDGSTS) double-buffered SMEM pipeline: global latency never touches a
// register scoreboard. SMEM in2 rows are zero-padded (4 floats each side) so
// the x-boundary handling vanishes from the hot loop AND from the epilogue.

#define CC 128
#define HH 96
#define WW 128
#define HW (HH * WW)

#define NTHR   288         // 9 warps: (ri,g) in 3x3
#define STAGES 64          // 2 channels per stage
#define W2     136         // padded in2 row: 4 + 128 + 4 floats

typedef unsigned long long ull;

__device__ __forceinline__ void fma2(ull& acc, ull a, ull b) {
    asm("fma.rn.f32x2 %0, %1, %2, %0;" : "+l"(acc) : "l"(a), "l"(b));
}

// pair (lo = hi of a, hi = lo of b)
__device__ __forceinline__ ull pkmid(ull a, ull b) {
    ull r;
    asm("{ .reg .b32 al, ah, bl, bh;\n\t"
        "  mov.b64 {al, ah}, %1;\n\t"
        "  mov.b64 {bl, bh}, %2;\n\t"
        "  mov.b64 %0, {ah, bl}; }"
        : "=l"(r) : "l"(a), "l"(b));
    return r;
}

__device__ __forceinline__ float2 unpk(ull v) {
    unsigned lo, hi;
    asm("mov.b64 {%0,%1}, %2;" : "=r"(lo), "=r"(hi) : "l"(v));
    return make_float2(__uint_as_float(lo), __uint_as_float(hi));
}

__device__ __forceinline__ void cp16(uint32_t dst, const float* src) {
    asm volatile("cp.async.cg.shared.global [%0], [%1], 16;"
                 :: "r"(dst), "l"(src) : "memory");
}

__global__ __launch_bounds__(NTHR, 1) void corr_kernel(
    const float* __restrict__ in1,
    const float* __restrict__ in2,
    float* __restrict__ out)
{
    // [buf][ch][row][col]
    __shared__ float s2[2][2][3][W2];      // in2 rows, zero-padded both ends
    __shared__ float s1[2][2][11][WW];     // in1 rows

    const int tid  = threadIdx.x;
    const int lane = tid & 31;
    const int w    = tid >> 5;          // 0..8
    const int g    = w % 3;             // dy group: dy = 3g..3g+2
    const int ri   = w / 3;             // 0..2: which in2 row of the tile
    const int b    = blockIdx.y;
    const int r0   = blockIdx.x * 3 - 4;
    const int r    = r0 + ri;           // in2 row, -4..100
    const int x0   = lane * 4;

    const float rowok = (r >= 0 && r < HH) ? 1.0f : 0.0f;

    // zero the pads once (cols 0..3 and 132..135 of every in2 smem row)
    if (tid < 96) {
        const int bu = tid / 48, ch = (tid / 24) & 1, rr = (tid / 8) % 3, k = tid & 7;
        s2[bu][ch][rr][(k < 4) ? k : (k + 128)] = 0.0f;
    }

    const float* p1base = in1 + (size_t)b * CC * HW;
    const float* p2base = in2 + (size_t)b * CC * HW;

    // ---- stage fill: 2 channels -> 2*(3*32 + 11*32) = 896 16B chunks ----
    #define FILL(BU, S)                                                       \
        do {                                                                  \
            for (int q = tid; q < 896; q += NTHR) {                           \
                const int ch = (q >= 448) ? 1 : 0;                            \
                const int qq = q - ch * 448;                                  \
                const int c  = 2 * (S) + ch;                                  \
                if (qq < 96) {                                                \
                    const int rr = qq >> 5, k = qq & 31;                      \
                    int rc = r0 + rr;                                         \
                    rc = rc < 0 ? 0 : (rc > HH - 1 ? HH - 1 : rc);            \
                    cp16((uint32_t)__cvta_generic_to_shared(                  \
                             &s2[BU][ch][rr][4 + (k << 2)]),                  \
                         p2base + (size_t)c * HW + rc * WW + (k << 2));       \
                } else {                                                      \
                    const int q1 = qq - 96, j = q1 >> 5, k = q1 & 31;         \
                    int y = r0 - 4 + j;                                       \
                    y = y < 0 ? 0 : (y > HH - 1 ? HH - 1 : y);                \
                    cp16((uint32_t)__cvta_generic_to_shared(                  \
                             &s1[BU][ch][j][k << 2]),                         \
                         p1base + (size_t)c * HW + y * WW + (k << 2));        \
                }                                                             \
            }                                                                 \
            asm volatile("cp.async.commit_group;" ::: "memory");              \
        } while (0)

    ull acc[3][9][2];
    #pragma unroll
    for (int t = 0; t < 3; t++)
        #pragma unroll
        for (int d = 0; d < 9; d++) {
            acc[t][d][0] = 0ull;
            acc[t][d][1] = 0ull;
        }

    const int jbase = ri + 8 - 3 * g;   // in1 smem row for t=0 (2..10)

    FILL(0, 0);
    FILL(1, 1);

    #pragma unroll 1
    for (int s = 0; s < STAGES; s++) {
        if (s < STAGES - 1)
            asm volatile("cp.async.wait_group 1;" ::: "memory");
        else
            asm volatile("cp.async.wait_group 0;" ::: "memory");
        __syncthreads();

        const int bu = s & 1;
        #pragma unroll
        for (int u = 0; u < 2; u++) {
            const ulonglong2* wr = (const ulonglong2*)&s2[bu][u][ri][x0];
            const ulonglong2 Lv = wr[0], Mv = wr[1], Rv = wr[2];
            const ulonglong2 A0 = *(const ulonglong2*)&s1[bu][u][jbase][x0];
            const ulonglong2 A1 = *(const ulonglong2*)&s1[bu][u][jbase - 1][x0];
            const ulonglong2 A2 = *(const ulonglong2*)&s1[bu][u][jbase - 2][x0];

            ull wp[11];
            wp[0] = Lv.x;  wp[2] = Lv.y;  wp[4]  = Mv.x;
            wp[6] = Mv.y;  wp[8] = Rv.x;  wp[10] = Rv.y;
            wp[1] = pkmid(Lv.x, Lv.y);
            wp[3] = pkmid(Lv.y, Mv.x);
            wp[5] = pkmid(Mv.x, Mv.y);
            wp[7] = pkmid(Mv.y, Rv.x);
            wp[9] = pkmid(Rv.x, Rv.y);

            #pragma unroll
            for (int d = 0; d < 9; d++) {
                fma2(acc[0][d][0], A0.x, wp[d]);
                fma2(acc[0][d][1], A0.y, wp[d + 2]);
                fma2(acc[1][d][0], A1.x, wp[d]);
                fma2(acc[1][d][1], A1.y, wp[d + 2]);
                fma2(acc[2][d][0], A2.x, wp[d]);
                fma2(acc[2][d][1], A2.y, wp[d + 2]);
            }
        }
        __syncthreads();

        if (s + 2 < STAGES) FILL(bu, s + 2);
    }
    #undef FILL

    // ---- epilogue: x-boundary zeros came free from the smem pads;
    //      only row validity needs masking/skipping ----
    #pragma unroll
    for (int t = 0; t < 3; t++) {
        const int y = r + 4 - (3 * g + t);
        if (y < 0 || y >= HH) continue;        // warp-uniform
        const int dy = 3 * g + t;
        #pragma unroll
        for (int d = 0; d < 9; d++) {
            const float2 lo = unpk(acc[t][d][0]);
            const float2 hi = unpk(acc[t][d][1]);
            float* po = out + (((((size_t)b * 9 + dy) * 9 + d) * HH + y) * WW) + x0;
            *(float4*)po = make_float4(lo.x * rowok, lo.y * rowok,
                                       hi.x * rowok, hi.y * rowok);
        }
    }
}

extern "C" void kernel_launch(void* const* d_in, const int* in_sizes, int n_in,
                              void* d_out, int out_size)
{
    const float* in1 = (const float*)d_in[0];
    const float* in2 = (const float*)d_in[1];
    float* out = (float*)d_out;

    // blockIdx.x = r-tile (35 tiles cover r = -4..100), blockIdx.y = batch
    dim3 grid(35, 8, 1);
    corr_kernel<<<grid, NTHR>>>(in1, in2, out);
}

// round 7
// speedup vs baseline: 1.9269x; 1.3629x over previous
#include <cuda_runtime.h>
#include <cstdint>

// Spatial correlation sampler: out[b][dy][dx][y][x] =
//   sum_c in1[b,c,y,x] * in2[b,c,y+dy-4,x+dx-4]   (zero padded), dy,dx in 0..8
//
// Round-7: cp.async SMEM pipeline (round 6) with:
//  - TRIPLE-buffered stages -> single __syncthreads per stage
//  - fully precomputed fill addressing (<=4 fixed slots per thread; per stage
//    just ptr + 2s*HW and dst + buf*BUFB) -> fill ALU ~eliminated
// Decomposition unchanged: warp = (in2 row ri, dy-group g), lane = 4 px,
// 27 f32x2 accumulators; SMEM in2 rows zero-padded so no x-boundary work.

#define CC 128
#define HH 96
#define WW 128
#define HW (HH * WW)

#define NTHR   288          // 9 warps: (ri,g) in 3x3
#define STAGES 64           // 2 channels per stage
#define W2     136          // padded row: 4 + 128 + 4 floats
#define CHF    (14 * W2)    // floats per channel slab (3 in2 + 11 in1 rows)
#define BUFF   (2 * CHF)    // floats per stage buffer (2 channels)
#define BUFB   (BUFF * 4)   // bytes per stage buffer

typedef unsigned long long ull;

__device__ __forceinline__ void fma2(ull& acc, ull a, ull b) {
    asm("fma.rn.f32x2 %0, %1, %2, %0;" : "+l"(acc) : "l"(a), "l"(b));
}

__device__ __forceinline__ ull pkmid(ull a, ull b) {
    ull r;
    asm("{ .reg .b32 al, ah, bl, bh;\n\t"
        "  mov.b64 {al, ah}, %1;\n\t"
        "  mov.b64 {bl, bh}, %2;\n\t"
        "  mov.b64 %0, {ah, bl}; }"
        : "=l"(r) : "l"(a), "l"(b));
    return r;
}

__device__ __forceinline__ float2 unpk(ull v) {
    unsigned lo, hi;
    asm("mov.b64 {%0,%1}, %2;" : "=r"(lo), "=r"(hi) : "l"(v));
    return make_float2(__uint_as_float(lo), __uint_as_float(hi));
}

__device__ __forceinline__ void cp16(uint32_t dst, const float* src) {
    asm volatile("cp.async.cg.shared.global [%0], [%1], 16;"
                 :: "r"(dst), "l"(src) : "memory");
}

__device__ __forceinline__ int clampi(int v, int lo, int hi) {
    return v < lo ? lo : (v > hi ? hi : v);
}

__global__ __launch_bounds__(NTHR, 1) void corr_kernel(
    const float* __restrict__ in1,
    const float* __restrict__ in2,
    float* __restrict__ out)
{
    // [buf(3)][ch(2)][row(14)][col(136)]; rows 0..2 = in2 (padded),
    // rows 3..13 = in1 (stored at col offset +4, same as in2 data)
    __shared__ float sm[3 * BUFF];

    const int tid  = threadIdx.x;
    const int lane = tid & 31;
    const int w    = tid >> 5;          // 0..8
    const int g    = w % 3;             // dy group: dy = 3g..3g+2
    const int ri   = w / 3;             // 0..2: which in2 row of the tile
    const int b    = blockIdx.y;
    const int r0   = blockIdx.x * 3 - 4;
    const int r    = r0 + ri;           // in2 row, -4..100
    const int x0   = lane * 4;

    const float rowok = (r >= 0 && r < HH) ? 1.0f : 0.0f;

    const float* p1base = in1 + (size_t)b * CC * HW;
    const float* p2base = in2 + (size_t)b * CC * HW;
    const uint32_t smb = (uint32_t)__cvta_generic_to_shared(sm);

    // ---- zero in2 pad columns in all 3 buffers (once) ----
    if (tid < 144) {
        const int bu = tid / 48, q = tid % 48;
        const int ch = q / 24, q2 = q % 24;
        const int rw = q2 / 8, k = q2 & 7;
        sm[(size_t)bu * BUFF + (ch * 14 + rw) * W2 + (k < 4 ? k : 128 + k)] = 0.0f;
    }

    // ---- precompute fill slots: row n = w + 9j of 28 (2ch x 14 rows) ----
    const float* ssrc[4];
    uint32_t     sdst[4];
    const int nslots = (w == 0) ? 4 : 3;   // warp-uniform
    #pragma unroll
    for (int j = 0; j < 4; j++) {
        const int n = w + 9 * j;
        if (n < 28) {
            const int ch = n / 14, rr = n % 14;
            int srow;
            const float* base;
            if (rr < 3) {
                srow = clampi(r0 + rr, 0, HH - 1);
                base = p2base;
            } else {
                srow = clampi(r0 - 4 + (rr - 3), 0, HH - 1);
                base = p1base;
            }
            ssrc[j] = base + (size_t)ch * HW + (size_t)srow * WW + x0;
            sdst[j] = smb + ((ch * 14 + rr) * W2 + 4 + x0) * 4;   // buf 0
        }
    }

    #define FILL(BUF, S)                                              \
        do {                                                          \
            const size_t co = (size_t)(2 * (S)) * HW;                 \
            const uint32_t bo = (uint32_t)(BUF) * BUFB;               \
            _Pragma("unroll")                                         \
            for (int j = 0; j < 4; j++)                               \
                if (j < nslots) cp16(sdst[j] + bo, ssrc[j] + co);     \
            asm volatile("cp.async.commit_group;" ::: "memory");      \
        } while (0)

    ull acc[3][9][2];
    #pragma unroll
    for (int t = 0; t < 3; t++)
        #pragma unroll
        for (int d = 0; d < 9; d++) {
            acc[t][d][0] = 0ull;
            acc[t][d][1] = 0ull;
        }

    // compute-side smem float offsets (buffer 0, channel 0)
    const int jbase = ri + 8 - 3 * g;            // 2..10
    const int winf  = ri * W2 + x0;              // window floats x0..x0+11
    int af[3];
    #pragma unroll
    for (int t = 0; t < 3; t++)
        af[t] = (3 + jbase - t) * W2 + 4 + x0;

    FILL(0, 0);
    FILL(1, 1);

    int bufc = 0;   // s % 3
    int buff = 2;   // (s+2) % 3

    #pragma unroll 1
    for (int s = 0; s < STAGES; s++) {
        if (s < STAGES - 1)
            asm volatile("cp.async.wait_group 1;" ::: "memory");
        else
            asm volatile("cp.async.wait_group 0;" ::: "memory");
        __syncthreads();

        const int boff = bufc * BUFF;
        #pragma unroll
        for (int u = 0; u < 2; u++) {
            const float* base = sm + boff + u * CHF;
            const ulonglong2* q = (const ulonglong2*)(base + winf);
            const ulonglong2 Lv = q[0], Mv = q[1], Rv = q[2];
            const ulonglong2 A0 = *(const ulonglong2*)(base + af[0]);
            const ulonglong2 A1 = *(const ulonglong2*)(base + af[1]);
            const ulonglong2 A2 = *(const ulonglong2*)(base + af[2]);

            ull wp[11];
            wp[0] = Lv.x;  wp[2] = Lv.y;  wp[4]  = Mv.x;
            wp[6] = Mv.y;  wp[8] = Rv.x;  wp[10] = Rv.y;
            wp[1] = pkmid(Lv.x, Lv.y);
            wp[3] = pkmid(Lv.y, Mv.x);
            wp[5] = pkmid(Mv.x, Mv.y);
            wp[7] = pkmid(Mv.y, Rv.x);
            wp[9] = pkmid(Rv.x, Rv.y);

            #pragma unroll
            for (int d = 0; d < 9; d++) {
                fma2(acc[0][d][0], A0.x, wp[d]);
                fma2(acc[0][d][1], A0.y, wp[d + 2]);
                fma2(acc[1][d][0], A1.x, wp[d]);
                fma2(acc[1][d][1], A1.y, wp[d + 2]);
                fma2(acc[2][d][0], A2.x, wp[d]);
                fma2(acc[2][d][1], A2.y, wp[d + 2]);
            }
        }

        // fill buffer (s+2)%3: its last consumers finished at stage s-1,
        // ordered by this stage's top barrier -> no second barrier needed
        if (s + 2 < STAGES) FILL(buff, s + 2);

        bufc = (bufc == 2) ? 0 : bufc + 1;
        buff = (buff == 2) ? 0 : buff + 1;
    }
    #undef FILL

    // ---- epilogue: x-boundary zeros came free from smem pads ----
    #pragma unroll
    for (int t = 0; t < 3; t++) {
        const int y = r + 4 - (3 * g + t);
        if (y < 0 || y >= HH) continue;        // warp-uniform
        const int dy = 3 * g + t;
        #pragma unroll
        for (int d = 0; d < 9; d++) {
            const float2 lo = unpk(acc[t][d][0]);
            const float2 hi = unpk(acc[t][d][1]);
            float* po = out + (((((size_t)b * 9 + dy) * 9 + d) * HH + y) * WW) + x0;
            *(float4*)po = make_float4(lo.x * rowok, lo.y * rowok,
                                       hi.x * rowok, hi.y * rowok);
        }
    }
}

extern "C" void kernel_launch(void* const* d_in, const int* in_sizes, int n_in,
                              void* d_out, int out_size)
{
    const float* in1 = (const float*)d_in[0];
    const float* in2 = (const float*)d_in[1];
    float* out = (float*)d_out;

    // blockIdx.x = r-tile (35 tiles cover r = -4..100), blockIdx.y = batch
    dim3 grid(35, 8, 1);
    corr_kernel<<<grid, NTHR>>>(in1, in2, out);
}